// round 3
// baseline (speedup 1.0000x reference)
#include <cuda_runtime.h>
#include <math.h>
#include <stdint.h>

// Noisy top-k MoE router for GB300 (sm_103a).
// x:[BS,2048] fp32, gate_w/noise_w:[2048,8], biases:[8], noise:[BS,8], top_k=2.
// out = concat(probs[BS,8] fp32, topk_idx[BS,2] as fp32)
//
//  - Both GEMVs fused: 16 outputs/row as 8 packed f32x2 accumulators.
//  - fma.rn.f32x2 halves FP32 FMA instruction count (Blackwell packed FMA).
//  - Combined 128 KB weight matrix in dynamic SMEM, permuted so lane-strided
//    reads are consecutive 8B words -> conflict-free LDS.64.
//  - Persistent grid (152 blocks x 256 thr), warp owns 4 rows/group.
//  - Depth-2 register prefetch of x (float4) to hide ~600-1000 cyc DRAM latency.
//  - 64-bit butterfly shuffle reduction; register-only top-2 + 2-way softmax.

static constexpr int Dk = 2048;   // hidden dim
static constexpr int Ek = 8;      // experts
static constexpr int Rk = 4;      // rows per warp group
static constexpr int WARPS = 8;
static constexpr int NTHREADS = WARPS * 32;
static constexpr int SMEM_BYTES = 8 * 2048 * 8;  // 8 planes x 2048 f32x2 pairs

__device__ __forceinline__ unsigned long long pack2(float x) {
    unsigned long long r;
    asm("mov.b64 %0, {%1, %1};" : "=l"(r) : "f"(x));
    return r;
}
__device__ __forceinline__ void fma2(unsigned long long& d, unsigned long long a,
                                     unsigned long long b) {
    asm("fma.rn.f32x2 %0, %1, %2, %0;" : "+l"(d) : "l"(a), "l"(b));
}
__device__ __forceinline__ void add2(unsigned long long& d, unsigned long long a) {
    asm("add.rn.f32x2 %0, %0, %1;" : "+l"(d) : "l"(a));
}
__device__ __forceinline__ float2 unpk(unsigned long long v) {
    float2 r;
    asm("mov.b64 {%0, %1}, %2;" : "=f"(r.x), "=f"(r.y) : "l"(v));
    return r;
}

extern "C" __global__ void __launch_bounds__(NTHREADS, 1)
router_kernel(const float* __restrict__ x,
              const float* __restrict__ gw,
              const float* __restrict__ gb,
              const float* __restrict__ nw,
              const float* __restrict__ nb,
              const float* __restrict__ noise,
              float* __restrict__ out_probs,
              float* __restrict__ out_idx,
              int BS, int write_idx)
{
    extern __shared__ unsigned long long ws[];  // [8 planes][2048 pairs], permuted

    // ---- Fill SMEM weights: plane p<4 = gate pairs (2p,2p+1), p>=4 = noise pairs.
    // Permutation: original d = chunk*128 + lane*4 + dd  ->  stored at
    //   chunk*128 + dd*32 + lane, so main-loop lanes read consecutive 8B words.
    for (int t = threadIdx.x; t < 8 * 2048; t += NTHREADS) {
        int p = t >> 11;        // 0..7
        int d = t & 2047;
        const float* src = (p < 4) ? gw : nw;
        int pp = p & 3;
        unsigned long long val =
            *(const unsigned long long*)(src + (size_t)d * Ek + pp * 2);
        int sidx = (d & ~127) + (d & 3) * 32 + ((d & 127) >> 2);
        ws[(p << 11) + sidx] = val;
    }

    // Bias registers (hoisted out of the group loop; L1/const-cached loads once).
    float gbr[Ek], nbr[Ek];
    #pragma unroll
    for (int e = 0; e < Ek; e++) { gbr[e] = gb[e]; nbr[e] = nb[e]; }

    __syncthreads();

    const int lane  = threadIdx.x & 31;
    const int warp  = threadIdx.x >> 5;
    const int gwarp = blockIdx.x * WARPS + warp;
    const int nwarp = gridDim.x * WARPS;
    const int ngroups = BS / Rk;

    for (int g = gwarp; g < ngroups; g += nwarp) {
        const float* x0 = x + (size_t)g * (Rk * Dk) + lane * 4;

        unsigned long long acc[Rk][8];
        #pragma unroll
        for (int r = 0; r < Rk; r++)
            #pragma unroll
            for (int p = 0; p < 8; p++) acc[r][p] = 0ull;

        // Depth-2 register prefetch buffers for x.
        float4 xbuf[2][Rk];
        #pragma unroll
        for (int r = 0; r < Rk; r++) {
            xbuf[0][r] = *(const float4*)(x0 + r * Dk);
            xbuf[1][r] = *(const float4*)(x0 + r * Dk + 128);
        }

        #pragma unroll 2
        for (int i = 0; i < 16; i++) {
            float4 xv[Rk];
            #pragma unroll
            for (int r = 0; r < Rk; r++) xv[r] = xbuf[i & 1][r];
            if (i < 14) {
                #pragma unroll
                for (int r = 0; r < Rk; r++)
                    xbuf[i & 1][r] = *(const float4*)(x0 + r * Dk + (i + 2) * 128);
            }
            const unsigned long long* wb = ws + i * 128 + lane;
            #pragma unroll
            for (int dd = 0; dd < 4; dd++) {
                unsigned long long w[8];
                #pragma unroll
                for (int p = 0; p < 8; p++)
                    w[p] = wb[(p << 11) + dd * 32];   // conflict-free LDS.64
                #pragma unroll
                for (int r = 0; r < Rk; r++) {
                    float xs = dd == 0 ? xv[r].x : dd == 1 ? xv[r].y
                             : dd == 2 ? xv[r].z : xv[r].w;
                    unsigned long long xx = pack2(xs);
                    #pragma unroll
                    for (int p = 0; p < 8; p++) fma2(acc[r][p], xx, w[p]);
                }
            }
        }

        // ---- Butterfly reduction across lanes (packed f32x2 adds).
        #pragma unroll
        for (int off = 16; off > 0; off >>= 1) {
            #pragma unroll
            for (int r = 0; r < Rk; r++)
                #pragma unroll
                for (int p = 0; p < 8; p++)
                    add2(acc[r][p], __shfl_xor_sync(0xffffffffu, acc[r][p], off));
        }

        // ---- Epilogue: lane r handles row g*Rk + r (compile-time selects,
        // no dynamic register indexing).
        if (lane < Rk) {
            unsigned long long v[8];
            #pragma unroll
            for (int p = 0; p < 8; p++)
                v[p] = lane == 0 ? acc[0][p] : lane == 1 ? acc[1][p]
                     : lane == 2 ? acc[2][p] : acc[3][p];

            int row = g * Rk + lane;
            float4 nz0 = *(const float4*)(noise + (size_t)row * Ek);
            float4 nz1 = *(const float4*)(noise + (size_t)row * Ek + 4);
            float nz[8] = {nz0.x, nz0.y, nz0.z, nz0.w, nz1.x, nz1.y, nz1.z, nz1.w};

            float noisy[8];
            #pragma unroll
            for (int p = 0; p < 4; p++) {
                float2 gp = unpk(v[p]);
                float2 np = unpk(v[p + 4]);
                int e0 = 2 * p, e1 = 2 * p + 1;
                float nl0 = np.x + nbr[e0];
                float nl1 = np.y + nbr[e1];
                float sp0 = nl0 > 20.f ? nl0 : log1pf(expf(nl0));
                float sp1 = nl1 > 20.f ? nl1 : log1pf(expf(nl1));
                noisy[e0] = gp.x + gbr[e0] + nz[e0] * sp0;
                noisy[e1] = gp.y + gbr[e1] + nz[e1] * sp1;
            }

            // top-2 (ties -> lowest index, matching jax.lax.top_k stability)
            int i1 = 0; float v1 = noisy[0];
            #pragma unroll
            for (int e = 1; e < 8; e++)
                if (noisy[e] > v1) { v1 = noisy[e]; i1 = e; }
            int i2 = -1; float v2 = -INFINITY;
            #pragma unroll
            for (int e = 0; e < 8; e++)
                if (e != i1 && noisy[e] > v2) { v2 = noisy[e]; i2 = e; }

            // softmax over {v1, v2}; all other experts -> 0
            float e2v = expf(v2 - v1);
            float inv = 1.0f / (1.0f + e2v);
            float p1 = inv, p2 = e2v * inv;

            float pr[8];
            #pragma unroll
            for (int e = 0; e < 8; e++)
                pr[e] = (e == i1) ? p1 : (e == i2) ? p2 : 0.0f;

            float4 s0 = make_float4(pr[0], pr[1], pr[2], pr[3]);
            float4 s1 = make_float4(pr[4], pr[5], pr[6], pr[7]);
            *(float4*)(out_probs + (size_t)row * Ek)     = s0;
            *(float4*)(out_probs + (size_t)row * Ek + 4) = s1;

            if (write_idx) {
                out_idx[(size_t)row * 2]     = (float)i1;
                out_idx[(size_t)row * 2 + 1] = (float)i2;
            }
        }
    }
}

extern "C" void kernel_launch(void* const* d_in, const int* in_sizes, int n_in,
                              void* d_out, int out_size)
{
    const float* x     = (const float*)d_in[0];
    const float* gw    = (const float*)d_in[1];
    const float* gb    = (const float*)d_in[2];
    const float* nw    = (const float*)d_in[3];
    const float* nb    = (const float*)d_in[4];
    const float* noise = (const float*)d_in[5];

    int BS = in_sizes[0] / Dk;            // 16384 for the given shapes
    float* probs  = (float*)d_out;
    float* idxout = probs + (size_t)BS * Ek;
    // Exact concat layout: probs [BS,8] then topk_idx [BS,2] (as output dtype).
    int write_idx = (out_size >= BS * (Ek + 2)) ? 1 : 0;

    cudaFuncSetAttribute(router_kernel,
                         cudaFuncAttributeMaxDynamicSharedMemorySize, SMEM_BYTES);
    router_kernel<<<152, NTHREADS, SMEM_BYTES>>>(
        x, gw, gb, nw, nb, noise, probs, idxout, BS, write_idx);
}

// round 11
// speedup vs baseline: 1.3153x; 1.3153x over previous
#include <cuda_runtime.h>
#include <math.h>
#include <stdint.h>

// Noisy top-k MoE router for GB300 (sm_103a).
// x:[BS,2048] fp32, gate_w/noise_w:[2048,8], biases:[8], noise:[BS,8], top_k=2.
// out = concat(probs[BS,8] fp32, topk_idx[BS,2] as fp32)
//
// R10 = R3 design, resubmitted (R3-R9: GPU acquisition timeouts; never ran).
//  - 512 threads (16 warps/SM, 4/SMSP) to double latency hiding vs the
//    measured 59.9us @ occ=12.4% issue=35% latency-bound baseline.
//  - Weight planes split across warp halves: lanes 0-15 gate, 16-31 noise.
//    (8B LDS phases = half-warps, so each phase reads one contiguous 128B
//    segment -> conflict-free.) Halves register pressure -> fits 128 regs.
//  - Same total LDS bytes and packed-fma2 count as the 256-thread version.
//  - Depth-2 register prefetch of x; 4-stage butterfly + 1 cross-half shuffle
//    (offset-16 swap hands full noise sums to gate lanes).

static constexpr int Dk = 2048;   // hidden dim
static constexpr int Ek = 8;      // experts
static constexpr int Rk = 4;      // rows per warp group
static constexpr int WARPS = 16;
static constexpr int NTHREADS = WARPS * 32;
static constexpr int SMEM_BYTES = 8 * 2048 * 8;  // 8 planes x 2048 f32x2 pairs

__device__ __forceinline__ unsigned long long pack2(float x) {
    unsigned long long r;
    asm("mov.b64 %0, {%1, %1};" : "=l"(r) : "f"(x));
    return r;
}
__device__ __forceinline__ void fma2(unsigned long long& d, unsigned long long a,
                                     unsigned long long b) {
    asm("fma.rn.f32x2 %0, %1, %2, %0;" : "+l"(d) : "l"(a), "l"(b));
}
__device__ __forceinline__ void add2(unsigned long long& d, unsigned long long a) {
    asm("add.rn.f32x2 %0, %0, %1;" : "+l"(d) : "l"(a));
}
__device__ __forceinline__ float2 unpk(unsigned long long v) {
    float2 r;
    asm("mov.b64 {%0, %1}, %2;" : "=f"(r.x), "=f"(r.y) : "l"(v));
    return r;
}

extern "C" __global__ void __launch_bounds__(NTHREADS, 1)
router_kernel(const float* __restrict__ x,
              const float* __restrict__ gw,
              const float* __restrict__ gb,
              const float* __restrict__ nw,
              const float* __restrict__ nb,
              const float* __restrict__ noise,
              float* __restrict__ out_probs,
              float* __restrict__ out_idx,
              int BS, int write_idx)
{
    extern __shared__ unsigned long long ws[];  // [8 planes][2048 pairs], permuted

    // ---- Fill SMEM weights. Plane p<4 = gate pairs (2p,2p+1); p>=4 = noise.
    // Main loop maps d = i*64 + hl*4 + dd  ->  sidx = i*64 + dd*16 + hl
    // so each half-warp phase reads 16 consecutive 8B words (128B segment).
    for (int t = threadIdx.x; t < 8 * 2048; t += NTHREADS) {
        int p = t >> 11;        // 0..7
        int d = t & 2047;
        const float* src = (p < 4) ? gw : nw;
        int pp = p & 3;
        unsigned long long val =
            *(const unsigned long long*)(src + (size_t)d * Ek + pp * 2);
        int sidx = (d & ~63) + (d & 3) * 16 + ((d & 63) >> 2);
        ws[(p << 11) + sidx] = val;
    }

    // Bias registers (loaded once).
    float gbr[Ek], nbr[Ek];
    #pragma unroll
    for (int e = 0; e < Ek; e++) { gbr[e] = gb[e]; nbr[e] = nb[e]; }

    __syncthreads();

    const int lane  = threadIdx.x & 31;
    const int hl    = lane & 15;        // position within half-warp
    const int hi    = lane >> 4;        // 0 = gate half, 1 = noise half
    const int warp  = threadIdx.x >> 5;
    const int gwarp = blockIdx.x * WARPS + warp;
    const int nwarp = gridDim.x * WARPS;
    const int ngroups = BS / Rk;

    for (int g = gwarp; g < ngroups; g += nwarp) {
        // Both halves read the same x addresses (coalescer broadcasts).
        const float* x0 = x + (size_t)g * (Rk * Dk) + hl * 4;

        unsigned long long acc[Rk][4];
        #pragma unroll
        for (int r = 0; r < Rk; r++)
            #pragma unroll
            for (int q = 0; q < 4; q++) acc[r][q] = 0ull;

        // Depth-2 register prefetch buffers for x (64 d-elems per iter).
        float4 xbuf[2][Rk];
        #pragma unroll
        for (int r = 0; r < Rk; r++) {
            xbuf[0][r] = *(const float4*)(x0 + r * Dk);
            xbuf[1][r] = *(const float4*)(x0 + r * Dk + 64);
        }

        #pragma unroll 2
        for (int i = 0; i < 32; i++) {
            float4 xv[Rk];
            #pragma unroll
            for (int r = 0; r < Rk; r++) xv[r] = xbuf[i & 1][r];
            if (i < 30) {
                #pragma unroll
                for (int r = 0; r < Rk; r++)
                    xbuf[i & 1][r] = *(const float4*)(x0 + r * Dk + (i + 2) * 64);
            }
            // hi half reads planes 4..7 (noise), low half planes 0..3 (gate).
            const unsigned long long* wb = ws + (hi << 13) + i * 64 + hl;
            #pragma unroll
            for (int dd = 0; dd < 4; dd++) {
                unsigned long long w[4];
                #pragma unroll
                for (int q = 0; q < 4; q++)
                    w[q] = wb[(q << 11) + dd * 16];   // conflict-free LDS.64
                #pragma unroll
                for (int r = 0; r < Rk; r++) {
                    float xs = dd == 0 ? xv[r].x : dd == 1 ? xv[r].y
                             : dd == 2 ? xv[r].z : xv[r].w;
                    unsigned long long xx = pack2(xs);
                    #pragma unroll
                    for (int q = 0; q < 4; q++) fma2(acc[r][q], xx, w[q]);
                }
            }
        }

        // ---- Butterfly reduction within each half-warp (offsets 8,4,2,1).
        #pragma unroll
        for (int off = 8; off > 0; off >>= 1) {
            #pragma unroll
            for (int r = 0; r < Rk; r++)
                #pragma unroll
                for (int q = 0; q < 4; q++)
                    add2(acc[r][q], __shfl_xor_sync(0xffffffffu, acc[r][q], off));
        }

        // ---- Cross-half exchange (warp-collective): gate lanes receive the
        // fully-reduced noise sums from lanes 16..31.
        unsigned long long nacc[Rk][4];
        #pragma unroll
        for (int r = 0; r < Rk; r++)
            #pragma unroll
            for (int q = 0; q < 4; q++)
                nacc[r][q] = __shfl_xor_sync(0xffffffffu, acc[r][q], 16);

        // ---- Epilogue: lane r (r<4, gate half) handles row g*Rk + r.
        if (lane < Rk) {
            unsigned long long vg[4], vn[4];
            #pragma unroll
            for (int q = 0; q < 4; q++) {
                vg[q] = lane == 0 ? acc[0][q] : lane == 1 ? acc[1][q]
                      : lane == 2 ? acc[2][q] : acc[3][q];
                vn[q] = lane == 0 ? nacc[0][q] : lane == 1 ? nacc[1][q]
                      : lane == 2 ? nacc[2][q] : nacc[3][q];
            }

            int row = g * Rk + lane;
            float4 nz0 = *(const float4*)(noise + (size_t)row * Ek);
            float4 nz1 = *(const float4*)(noise + (size_t)row * Ek + 4);
            float nz[8] = {nz0.x, nz0.y, nz0.z, nz0.w, nz1.x, nz1.y, nz1.z, nz1.w};

            float noisy[8];
            #pragma unroll
            for (int q = 0; q < 4; q++) {
                float2 gp = unpk(vg[q]);
                float2 np = unpk(vn[q]);
                int e0 = 2 * q, e1 = 2 * q + 1;
                float nl0 = np.x + nbr[e0];
                float nl1 = np.y + nbr[e1];
                float sp0 = nl0 > 20.f ? nl0 : log1pf(expf(nl0));
                float sp1 = nl1 > 20.f ? nl1 : log1pf(expf(nl1));
                noisy[e0] = gp.x + gbr[e0] + nz[e0] * sp0;
                noisy[e1] = gp.y + gbr[e1] + nz[e1] * sp1;
            }

            // top-2 (ties -> lowest index, matching jax.lax.top_k stability)
            int i1 = 0; float v1 = noisy[0];
            #pragma unroll
            for (int e = 1; e < 8; e++)
                if (noisy[e] > v1) { v1 = noisy[e]; i1 = e; }
            int i2 = -1; float v2 = -INFINITY;
            #pragma unroll
            for (int e = 0; e < 8; e++)
                if (e != i1 && noisy[e] > v2) { v2 = noisy[e]; i2 = e; }

            // softmax over {v1, v2}; all other experts -> 0
            float e2v = expf(v2 - v1);
            float inv = 1.0f / (1.0f + e2v);
            float p1 = inv, p2 = e2v * inv;

            float pr[8];
            #pragma unroll
            for (int e = 0; e < 8; e++)
                pr[e] = (e == i1) ? p1 : (e == i2) ? p2 : 0.0f;

            float4 s0 = make_float4(pr[0], pr[1], pr[2], pr[3]);
            float4 s1 = make_float4(pr[4], pr[5], pr[6], pr[7]);
            *(float4*)(out_probs + (size_t)row * Ek)     = s0;
            *(float4*)(out_probs + (size_t)row * Ek + 4) = s1;

            if (write_idx) {
                out_idx[(size_t)row * 2]     = (float)i1;
                out_idx[(size_t)row * 2 + 1] = (float)i2;
            }
        }
    }
}

extern "C" void kernel_launch(void* const* d_in, const int* in_sizes, int n_in,
                              void* d_out, int out_size)
{
    const float* x     = (const float*)d_in[0];
    const float* gw    = (const float*)d_in[1];
    const float* gb    = (const float*)d_in[2];
    const float* nw    = (const float*)d_in[3];
    const float* nb    = (const float*)d_in[4];
    const float* noise = (const float*)d_in[5];

    int BS = in_sizes[0] / Dk;            // 16384 for the given shapes
    float* probs  = (float*)d_out;
    float* idxout = probs + (size_t)BS * Ek;
    // Exact concat layout: probs [BS,8] then topk_idx [BS,2] (as output dtype).
    int write_idx = (out_size >= BS * (Ek + 2)) ? 1 : 0;

    cudaFuncSetAttribute(router_kernel,
                         cudaFuncAttributeMaxDynamicSharedMemorySize, SMEM_BYTES);
    router_kernel<<<152, NTHREADS, SMEM_BYTES>>>(
        x, gw, gb, nw, nb, noise, probs, idxout, BS, write_idx);
}